// round 9
// baseline (speedup 1.0000x reference)
#include <cuda_runtime.h>
#include <cuda_bf16.h>
#include <cstdint>

// Integration_4123168604342
// x: (T=128, B=4, E=10000, F=16) f32, dummy_index: int scalar
// out: (128, 4, 10000, 15) f32 = tanh(cumsum_T(f * dt))
//
// R9: phase-batched depth-16 pipeline. Each 16-row block runs three phases:
//   A) 16x register-only compute (shfl + fma + tanh), writing the result
//      back into the same buffer register (no extra register cost)
//   B) 16 back-to-back STG.32  (per-warp ~1.9KB write burst)
//   C) 16 back-to-back LDG.32 (__ldcs) for the next 16 rows (2KB read burst)
// Identical traffic/instruction count to R5; only arrival pattern at the
// memory controller changes — bursty writes/reads cut DRAM bus turnarounds.

#define T_DIM   128
#define B_DIM   4
#define E_DIM   10000
#define F_DIM   16
#define FO_DIM  15
#define DEPTH   16
#define BE_DIM  (B_DIM * E_DIM)               // 40000 groups
#define STRIDE_T   ((size_t)BE_DIM * F_DIM)   // 640000 floats per t (input)
#define STRIDE_TO  ((size_t)BE_DIM * FO_DIM)  // 600000 floats per t (output)

__device__ __forceinline__ float tanh_fast(float x) {
    float y;
    asm("tanh.approx.f32 %0, %1;" : "=f"(y) : "f"(x));
    return y;
}

__global__ __launch_bounds__(256)
void integration_kernel(const float* __restrict__ x,
                        const int* __restrict__ didx,
                        float* __restrict__ out) {
    const int gid   = blockIdx.x * blockDim.x + threadIdx.x;
    const int group = gid >> 4;       // (b,e) flat index
    const int lane  = gid & 15;       // channel

    const int d = *didx;              // dummy (time) channel
    const bool is_t = (lane == d);
    const int oc = lane - (lane > d ? 1 : 0);   // output channel for non-t lanes

    const float* __restrict__ xp = x + (size_t)group * F_DIM + lane;
    float* __restrict__ op = out + (size_t)group * FO_DIM + oc;

    // ---- prologue: rows 0..15 in flight (16-wide read burst) ----
    float b0  = __ldcs(xp);
    float b1  = __ldcs(xp + STRIDE_T);
    float b2  = __ldcs(xp + 2 * STRIDE_T);
    float b3  = __ldcs(xp + 3 * STRIDE_T);
    float b4  = __ldcs(xp + 4 * STRIDE_T);
    float b5  = __ldcs(xp + 5 * STRIDE_T);
    float b6  = __ldcs(xp + 6 * STRIDE_T);
    float b7  = __ldcs(xp + 7 * STRIDE_T);
    float b8  = __ldcs(xp + 8 * STRIDE_T);
    float b9  = __ldcs(xp + 9 * STRIDE_T);
    float b10 = __ldcs(xp + 10 * STRIDE_T);
    float b11 = __ldcs(xp + 11 * STRIDE_T);
    float b12 = __ldcs(xp + 12 * STRIDE_T);
    float b13 = __ldcs(xp + 13 * STRIDE_T);
    float b14 = __ldcs(xp + 14 * STRIDE_T);
    float b15 = __ldcs(xp + 15 * STRIDE_T);

    float acc = 0.0f;
    float prev_t;

    // Phase A step: consume raw b as row (base+k), overwrite b with tanh(acc).
    // (shfl of b happens before the overwrite; t-lane's overwritten value is
    // never stored.)
#define COMPUTE(bv) do {                                        \
        const float tc = __shfl_sync(0xFFFFFFFFu, (bv), d, 16); \
        acc = fmaf((bv), tc - prev_t, acc);                     \
        (bv) = tanh_fast(acc);                                  \
        prev_t = tc;                                            \
    } while (0)

#define STORE(bv, k) do {                                                   \
        if (!is_t) op[(size_t)(base + (k)) * STRIDE_TO] = (bv);             \
    } while (0)

#define LOAD(bv, k) do {                                                    \
        (bv) = __ldcs(xp + (size_t)(base + (k) + DEPTH) * STRIDE_T);        \
    } while (0)

    #pragma unroll 1
    for (int base = 0; base < T_DIM; base += DEPTH) {
        // ---- phase A: 16x register-only compute ----
        if (base == 0) {
            // t=0 special: dt0 = t[0] + t[1]
            const float t0 = __shfl_sync(0xFFFFFFFFu, b0, d, 16);
            const float t1 = __shfl_sync(0xFFFFFFFFu, b1, d, 16);
            acc = b0 * (t0 + t1);
            b0 = tanh_fast(acc);
            prev_t = t0;
        } else {
            COMPUTE(b0);
        }
        COMPUTE(b1);  COMPUTE(b2);  COMPUTE(b3);
        COMPUTE(b4);  COMPUTE(b5);  COMPUTE(b6);  COMPUTE(b7);
        COMPUTE(b8);  COMPUTE(b9);  COMPUTE(b10); COMPUTE(b11);
        COMPUTE(b12); COMPUTE(b13); COMPUTE(b14); COMPUTE(b15);

        // ---- phase B: 16 back-to-back stores (write burst) ----
        STORE(b0, 0);   STORE(b1, 1);   STORE(b2, 2);   STORE(b3, 3);
        STORE(b4, 4);   STORE(b5, 5);   STORE(b6, 6);   STORE(b7, 7);
        STORE(b8, 8);   STORE(b9, 9);   STORE(b10, 10); STORE(b11, 11);
        STORE(b12, 12); STORE(b13, 13); STORE(b14, 14); STORE(b15, 15);

        // ---- phase C: 16 back-to-back loads for next block (read burst) ----
        if (base + DEPTH < T_DIM) {
            LOAD(b0, 0);   LOAD(b1, 1);   LOAD(b2, 2);   LOAD(b3, 3);
            LOAD(b4, 4);   LOAD(b5, 5);   LOAD(b6, 6);   LOAD(b7, 7);
            LOAD(b8, 8);   LOAD(b9, 9);   LOAD(b10, 10); LOAD(b11, 11);
            LOAD(b12, 12); LOAD(b13, 13); LOAD(b14, 14); LOAD(b15, 15);
        }
    }

#undef COMPUTE
#undef STORE
#undef LOAD
}

extern "C" void kernel_launch(void* const* d_in, const int* in_sizes, int n_in,
                              void* d_out, int out_size) {
    const float* x   = (const float*)d_in[0];
    const int* didx  = (const int*)d_in[1];
    float* out       = (float*)d_out;

    const int total_threads = BE_DIM * 16;        // 640000
    const int block = 256;
    const int grid = total_threads / block;       // 2500 exact
    integration_kernel<<<grid, block>>>(x, didx, out);
}

// round 10
// speedup vs baseline: 1.1023x; 1.1023x over previous
#include <cuda_runtime.h>
#include <cuda_bf16.h>
#include <cstdint>

// Integration_4123168604342
// x: (T=128, B=4, E=10000, F=16) f32, dummy_index: int scalar
// out: (128, 4, 10000, 15) f32 = tanh(cumsum_T(f * dt))
//
// R10: exact R5 pipeline (scalar mapping, depth-16 rotating buffers, plain
// loads/stores) with BLOCK = 512. A 512-thread block covers 32 groups, so its
// per-row output span is 32*15*4 = 1920 B = exactly 15 x 128B lines: no
// output L2 line is ever shared between blocks (256-thread blocks wrote 960 B
// spans -> every block boundary split a line across waves, forcing partial
// dirty evictions + ECC RMW on ~13% of output lines).

#define T_DIM   128
#define B_DIM   4
#define E_DIM   10000
#define F_DIM   16
#define FO_DIM  15
#define DEPTH   16
#define BE_DIM  (B_DIM * E_DIM)               // 40000 groups
#define STRIDE_T   ((size_t)BE_DIM * F_DIM)   // 640000 floats per t (input)
#define STRIDE_TO  ((size_t)BE_DIM * FO_DIM)  // 600000 floats per t (output)

__device__ __forceinline__ float tanh_fast(float x) {
    float y;
    asm("tanh.approx.f32 %0, %1;" : "=f"(y) : "f"(x));
    return y;
}

__global__ __launch_bounds__(512)
void integration_kernel(const float* __restrict__ x,
                        const int* __restrict__ didx,
                        float* __restrict__ out) {
    const int gid   = blockIdx.x * blockDim.x + threadIdx.x;
    const int group = gid >> 4;       // (b,e) flat index
    const int lane  = gid & 15;       // channel

    const int d = *didx;              // dummy (time) channel
    const bool is_t = (lane == d);
    const int oc = lane - (lane > d ? 1 : 0);   // output channel for non-t lanes

    const float* __restrict__ xp = x + (size_t)group * F_DIM + lane;
    float* __restrict__ op = out + (size_t)group * FO_DIM + oc;

    // ---- prologue: rows 0..15 in flight ----
    float b0  = xp[0];
    float b1  = xp[STRIDE_T];
    float b2  = xp[2 * STRIDE_T];
    float b3  = xp[3 * STRIDE_T];
    float b4  = xp[4 * STRIDE_T];
    float b5  = xp[5 * STRIDE_T];
    float b6  = xp[6 * STRIDE_T];
    float b7  = xp[7 * STRIDE_T];
    float b8  = xp[8 * STRIDE_T];
    float b9  = xp[9 * STRIDE_T];
    float b10 = xp[10 * STRIDE_T];
    float b11 = xp[11 * STRIDE_T];
    float b12 = xp[12 * STRIDE_T];
    float b13 = xp[13 * STRIDE_T];
    float b14 = xp[14 * STRIDE_T];
    float b15 = xp[15 * STRIDE_T];

    const float t0 = __shfl_sync(0xFFFFFFFFu, b0, d, 16);
    const float t1 = __shfl_sync(0xFFFFFFFFu, b1, d, 16);

    // t = 0: dt0 = t[0] + t[1]
    float acc = b0 * (t0 + t1);
    if (!is_t) op[0] = tanh_fast(acc);
    float prev_t = t0;

    // consume buffer bv as row (base+k), then reload bv from row (base+k+DEPTH)
#define STEP(bv, k) do {                                                    \
        const float tc = __shfl_sync(0xFFFFFFFFu, (bv), d, 16);             \
        acc = fmaf((bv), tc - prev_t, acc);                                 \
        if (!is_t) op[(size_t)(base + (k)) * STRIDE_TO] = tanh_fast(acc);   \
        prev_t = tc;                                                        \
        (bv) = xp[(size_t)(base + (k) + DEPTH) * STRIDE_T];                 \
    } while (0)

#define STEP_NOLOAD(bv, k) do {                                             \
        const float tc = __shfl_sync(0xFFFFFFFFu, (bv), d, 16);             \
        acc = fmaf((bv), tc - prev_t, acc);                                 \
        if (!is_t) op[(size_t)(base + (k)) * STRIDE_TO] = tanh_fast(acc);   \
        prev_t = tc;                                                        \
    } while (0)

    // ---- steady state: rows 0..111 consumed, rows 16..127 reloaded ----
    #pragma unroll 1
    for (int base = 0; base < T_DIM - DEPTH; base += DEPTH) {
        if (base > 0) STEP(b0, 0);
        else          b0 = xp[(size_t)DEPTH * STRIDE_T];   // row 0 already done
        STEP(b1,  1);
        STEP(b2,  2);
        STEP(b3,  3);
        STEP(b4,  4);
        STEP(b5,  5);
        STEP(b6,  6);
        STEP(b7,  7);
        STEP(b8,  8);
        STEP(b9,  9);
        STEP(b10, 10);
        STEP(b11, 11);
        STEP(b12, 12);
        STEP(b13, 13);
        STEP(b14, 14);
        STEP(b15, 15);
    }

    // ---- epilogue: rows 112..127, no more loads ----
    {
        const int base = T_DIM - DEPTH;
        STEP_NOLOAD(b0,  0);
        STEP_NOLOAD(b1,  1);
        STEP_NOLOAD(b2,  2);
        STEP_NOLOAD(b3,  3);
        STEP_NOLOAD(b4,  4);
        STEP_NOLOAD(b5,  5);
        STEP_NOLOAD(b6,  6);
        STEP_NOLOAD(b7,  7);
        STEP_NOLOAD(b8,  8);
        STEP_NOLOAD(b9,  9);
        STEP_NOLOAD(b10, 10);
        STEP_NOLOAD(b11, 11);
        STEP_NOLOAD(b12, 12);
        STEP_NOLOAD(b13, 13);
        STEP_NOLOAD(b14, 14);
        STEP_NOLOAD(b15, 15);
    }

#undef STEP
#undef STEP_NOLOAD
}

extern "C" void kernel_launch(void* const* d_in, const int* in_sizes, int n_in,
                              void* d_out, int out_size) {
    const float* x   = (const float*)d_in[0];
    const int* didx  = (const int*)d_in[1];
    float* out       = (float*)d_out;

    const int total_threads = BE_DIM * 16;        // 640000
    const int block = 512;                        // 32 groups: 1920B = 15 lines/row
    const int grid = total_threads / block;       // 1250 exact
    integration_kernel<<<grid, block>>>(x, didx, out);
}